// round 5
// baseline (speedup 1.0000x reference)
#include <cuda_runtime.h>
#include <cstdint>
#include <math.h>

#define KB 128      // batch k
#define NN 2048     // nodes
#define DD 512      // dim

// Scratch (no allocations allowed -> device globals)
__device__ float g_q[KB * DD];
__device__ float g_r[KB * DD];
__device__ float g_exp[KB * NN];            // exp(compat) at original node index
__device__ float g_rowsum[KB];
__device__ unsigned short g_idx[KB * NN];   // compacted unmasked node indices
__device__ int g_cnt[KB];
__device__ int g_bar;                        // monotonic ticket barrier counter

// ---------------------------------------------------------------------------
// Mask dtype sniff: 0 = int32 (0/1), 1 = float32 (0.0/1.0), 2 = uint8.
// ---------------------------------------------------------------------------
__device__ __forceinline__ int sniff_mask(const unsigned char* mask) {
    const unsigned* mw = (const unsigned*)mask;
    bool i32 = true, f32 = true;
    #pragma unroll
    for (int i = 0; i < 16; i++) {
        unsigned w = mw[i];
        i32 = i32 && (w <= 1u);
        f32 = f32 && (w == 0u || w == 0x3F800000u);
    }
    return i32 ? 0 : (f32 ? 1 : 2);
}

__device__ __forceinline__ bool mask_at(const unsigned char* mask, int mode, size_t gi) {
    if (mode == 0) return ((const int*)mask)[gi] != 0;
    if (mode == 1) return ((const float*)mask)[gi] != 0.f;
    return mask[gi] != 0;
}

// ---------------------------------------------------------------------------
// Fused prep kernel, grid = 96 CTAs x 256 threads (all co-resident on 148 SMs).
//   CTAs  0..63 : q tile (16x64) -> ticket barrier over 64 CTAs -> r tile
//   CTAs 64..95 : mask compaction, 4 rows each (independent of gemm work)
// MODE 0: g_q[m,n] = sum_kk ctx[m,kk] * Wq[n,kk]
// MODE 1: g_r[m,n] = sum_kk g_q[m,kk] * Wk[kk,n]... (B indexed [kk][n])
// ---------------------------------------------------------------------------
#define PBM 16
#define PBN 64
#define PBK 32

struct PrepSmem {
    float As[PBK][PBM + 1];
    float Bs[PBK][PBN + 4];
};

template<int MODE>
__device__ void gemm_phase(const float* __restrict__ A,
                           const float* __restrict__ B,
                           float* __restrict__ out,
                           int tileId, PrepSmem& sm) {
    int tid = threadIdx.x;
    int tx = tid & 15;     // 4 cols each
    int ty = tid >> 4;     // 16 rows
    int m0 = (tileId & 7) * PBM;     // 8 m-tiles
    int n0 = (tileId >> 3) * PBN;    // 8 n-tiles

    float acc0 = 0.f, acc1 = 0.f, acc2 = 0.f, acc3 = 0.f;

    for (int k0 = 0; k0 < DD; k0 += PBK) {
        // A tile 16m x 32k -> transposed As[kk][m]; 128 f4 loads (threads 0..127)
        if (tid < 128) {
            int m  = tid >> 3;
            int c4 = (tid & 7) * 4;
            float4 v = *(const float4*)&A[(size_t)(m0 + m) * DD + k0 + c4];
            sm.As[c4 + 0][m] = v.x; sm.As[c4 + 1][m] = v.y;
            sm.As[c4 + 2][m] = v.z; sm.As[c4 + 3][m] = v.w;
        }
        // B tile 32k x 64n -> Bs[kk][n]; 512 f4 loads, 2 per thread
        #pragma unroll
        for (int r = 0; r < 2; r++) {
            int idx = tid + r * 256;
            if (MODE == 0) {
                int n = idx >> 3, c4 = (idx & 7) * 4;   // vector along k
                float4 v = *(const float4*)&B[(size_t)(n0 + n) * DD + k0 + c4];
                sm.Bs[c4 + 0][n] = v.x; sm.Bs[c4 + 1][n] = v.y;
                sm.Bs[c4 + 2][n] = v.z; sm.Bs[c4 + 3][n] = v.w;
            } else {
                int kk = idx >> 4, c4 = (idx & 15) * 4; // vector along n
                float4 v = *(const float4*)&B[(size_t)(k0 + kk) * DD + n0 + c4];
                *(float4*)&sm.Bs[kk][c4] = v;
            }
        }
        __syncthreads();

        #pragma unroll
        for (int kk = 0; kk < PBK; kk++) {
            float a = sm.As[kk][ty];
            float4 b = *(const float4*)&sm.Bs[kk][tx * 4];
            acc0 += a * b.x; acc1 += a * b.y;
            acc2 += a * b.z; acc3 += a * b.w;
        }
        __syncthreads();
    }

    *(float4*)&out[(size_t)(m0 + ty) * DD + n0 + tx * 4]
        = make_float4(acc0, acc1, acc2, acc3);
}

__global__ void __launch_bounds__(256)
prep_kernel(const float* __restrict__ ctx,
            const float* __restrict__ Wq,
            const float* __restrict__ Wk,
            const unsigned char* __restrict__ mask) {
    __shared__ PrepSmem sm;
    int bid = blockIdx.x;
    int tid = threadIdx.x;

    if (bid < 64) {
        // -------- phase 1: q = ctx @ Wq^T --------
        gemm_phase<0>(ctx, Wq, g_q, bid, sm);

        // -------- ticket barrier over the 64 gemm CTAs --------
        __shared__ int s_target;
        if (tid == 0) {
            __threadfence();
            int old = atomicAdd(&g_bar, 1);
            s_target = (old & ~63) + 64;
        }
        __syncthreads();
        if (tid == 0) {
            volatile int* vb = &g_bar;
            while (*vb < s_target) { }
            __threadfence();
        }
        __syncthreads();

        // -------- phase 2: r = q @ Wk --------
        gemm_phase<1>(g_q, Wk, g_r, bid, sm);
    } else {
        // -------- compaction: rows 4*(bid-64) .. +3 --------
        int mode = sniff_mask(mask);
        int wid  = tid >> 5;
        int lane = tid & 31;
        __shared__ int warp_sums[8];
        __shared__ int base_s;

        for (int rr = 0; rr < 4; rr++) {
            int k = (bid - 64) * 4 + rr;
            if (tid == 0) { base_s = 0; g_rowsum[k] = 0.f; }
            __syncthreads();
            for (int j = 0; j < 8; j++) {
                int n = j * 256 + tid;
                bool um = !mask_at(mask, mode, (size_t)k * NN + n);
                unsigned bal = __ballot_sync(0xFFFFFFFFu, um);
                int wpre = __popc(bal & ((1u << lane) - 1u));
                if (lane == 0) warp_sums[wid] = __popc(bal);
                __syncthreads();
                int wbase = 0;
                #pragma unroll
                for (int w = 0; w < 8; w++) if (w < wid) wbase += warp_sums[w];
                if (um) g_idx[(size_t)k * NN + base_s + wbase + wpre] = (unsigned short)n;
                __syncthreads();
                if (tid == 0) {
                    int tot = 0;
                    #pragma unroll
                    for (int w = 0; w < 8; w++) tot += warp_sums[w];
                    base_s += tot;
                }
                __syncthreads();
            }
            if (tid == 0) g_cnt[k] = base_s;
            __syncthreads();
        }
    }
}

// ---------------------------------------------------------------------------
// Streaming dot over compacted nodes, balanced strided distribution.
// grid (16, 128) x 256 threads. Warp wg = blockIdx.x*8+warp (0..127 per k).
// Each iteration processes 4 nodes (slots s, s+128, s+256, s+384):
// 16 independent LDG.128 in flight per warp.
//   e = exp( tanh(clip(r[k]·node, -10, 10)) / sqrt(512) )
// ---------------------------------------------------------------------------
__global__ void __launch_bounds__(256, 2)
dot_kernel(const float* __restrict__ nodes) {
    int k    = blockIdx.y;
    int tid  = threadIdx.x;
    int warp = tid >> 5;
    int lane = tid & 31;
    int cnt  = g_cnt[k];

    const float4* r4 = (const float4*)(g_r + (size_t)k * DD);
    float4 r0 = __ldg(r4 + lane);
    float4 r1 = __ldg(r4 + lane + 32);
    float4 r2 = __ldg(r4 + lane + 64);
    float4 r3 = __ldg(r4 + lane + 96);

    const float4* base = (const float4*)(nodes + (size_t)k * NN * DD);
    const unsigned short* idx = g_idx + (size_t)k * NN;
    int wg = blockIdx.x * 8 + warp;     // 0..127

    const float inv_sqrt_d = 0.04419417382415922f;  // 1/sqrt(512)
    float wsum = 0.f;

    for (int s = wg; s < cnt; s += 512) {
        bool val[4];
        int nidx[4];
        #pragma unroll
        for (int i = 0; i < 4; i++) {
            int si = s + i * 128;
            val[i]  = si < cnt;
            nidx[i] = val[i] ? (int)idx[si] : 0;   // clamp: harmless dummy load
        }
        float4 A[4][4];
        #pragma unroll
        for (int i = 0; i < 4; i++) {
            const float4* p = base + (size_t)nidx[i] * (DD / 4);
            A[i][0] = __ldcs(p + lane);
            A[i][1] = __ldcs(p + lane + 32);
            A[i][2] = __ldcs(p + lane + 64);
            A[i][3] = __ldcs(p + lane + 96);
        }
        float sv[4];
        #pragma unroll
        for (int i = 0; i < 4; i++) {
            sv[i] = A[i][0].x * r0.x + A[i][0].y * r0.y + A[i][0].z * r0.z + A[i][0].w * r0.w
                  + A[i][1].x * r1.x + A[i][1].y * r1.y + A[i][1].z * r1.z + A[i][1].w * r1.w
                  + A[i][2].x * r2.x + A[i][2].y * r2.y + A[i][2].z * r2.z + A[i][2].w * r2.w
                  + A[i][3].x * r3.x + A[i][3].y * r3.y + A[i][3].z * r3.z + A[i][3].w * r3.w;
        }
        #pragma unroll
        for (int o = 16; o > 0; o >>= 1) {
            #pragma unroll
            for (int i = 0; i < 4; i++)
                sv[i] += __shfl_xor_sync(0xFFFFFFFFu, sv[i], o);
        }
        if (lane == 0) {
            #pragma unroll
            for (int i = 0; i < 4; i++) {
                if (val[i]) {
                    float e = __expf(tanhf(fminf(fmaxf(sv[i], -10.f), 10.f)) * inv_sqrt_d);
                    g_exp[(size_t)k * NN + nidx[i]] = e;
                    wsum += e;
                }
            }
        }
    }

    __shared__ float ws[8];
    if (lane == 0) ws[warp] = wsum;
    __syncthreads();
    if (tid == 0) {
        float s = 0.f;
        #pragma unroll
        for (int w = 0; w < 8; w++) s += ws[w];
        if (s != 0.f) atomicAdd(&g_rowsum[k], s);
    }
}

// ---------------------------------------------------------------------------
// Normalize: out = masked ? 0 : e / rowsum.  One CTA per row, 512 thr x 4.
// ---------------------------------------------------------------------------
__global__ void normalize_kernel(const unsigned char* __restrict__ mask,
                                 float* __restrict__ out) {
    int k   = blockIdx.x;
    int tid = threadIdx.x;
    int mode = sniff_mask(mask);

    float inv = 1.f / g_rowsum[k];
    int n0 = tid * 4;
    size_t gi = (size_t)k * NN + n0;

    float4 e = *(const float4*)&g_exp[gi];
    float r[4] = {e.x, e.y, e.z, e.w};
    float o[4];
    #pragma unroll
    for (int j = 0; j < 4; j++) {
        bool m = mask_at(mask, mode, gi + j);
        o[j] = m ? 0.f : r[j] * inv;
    }
    *(float4*)&out[gi] = make_float4(o[0], o[1], o[2], o[3]);
}

// ---------------------------------------------------------------------------
extern "C" void kernel_launch(void* const* d_in, const int* in_sizes, int n_in,
                              void* d_out, int out_size) {
    const float* ctx   = (const float*)d_in[0];  // [128, 512]
    const float* nodes = (const float*)d_in[1];  // [128, 2048, 512]
    const unsigned char* mask = (const unsigned char*)d_in[2];  // [128, 2048]
    const float* Wq    = (const float*)d_in[3];  // [512, 512]
    const float* Wk    = (const float*)d_in[4];  // [512, 512]
    // d_in[5] = Wv: dead code in the reference output, skipped.
    float* out = (float*)d_out;                  // [128, 2048]

    prep_kernel<<<96, 256>>>(ctx, Wq, Wk, mask);   // q, r, compaction (fused)
    dot_kernel<<<dim3(16, KB), 256>>>(nodes);      // exp(compat), row sums
    normalize_kernel<<<KB, 512>>>(mask, out);      // final weights
}